// round 3
// baseline (speedup 1.0000x reference)
#include <cuda_runtime.h>
#include <cstdint>

// ---------------- problem constants ----------------
#define BATCH   1024
#define TDIM    4
#define DIN     768
#define DSAE    16384
#define KSUM    (TDIM*DIN)       // 3072
#define TOPK    64
#define PFX0    8192
#define NBT     (BATCH*TDIM)     // 4096

// ---------------- device scratch (no allocations allowed) ----------------
__device__ float g_pre[(size_t)BATCH*DSAE];     // 64 MiB pre-activations
__device__ int   g_inv[TDIM*DSAE];              // inverse permutation
__device__ int   g_tk_idx[BATCH*TOPK];
__device__ float g_tk_val[BATCH*TOPK];          // relu'd values
__device__ float g_err[NBT];                    // per-(b,t) e0+e1

// ---------------- helpers ----------------
__device__ __forceinline__ unsigned fkey(float f) {
    unsigned u = __float_as_uint(f);
    return (u & 0x80000000u) ? ~u : (u | 0x80000000u);  // monotone: larger float -> larger key
}

// ---------------- K1: inverse permutation ----------------
__global__ void k_inv(const int* __restrict__ perm) {
    int i = blockIdx.x * blockDim.x + threadIdx.x;
    if (i < TDIM*DSAE) {
        int t = i / DSAE;
        g_inv[t*DSAE + perm[i]] = i % DSAE;
    }
}

// ---------------- K2: encoder SGEMM  C = X(1024x3072) * W(3072x16384) + bias
// 128x128 tile, BK=16, 256 threads, 8x8 micro-tile, register-staged double buffer.
#define BM 128
#define BN 128
#define BK 16
__global__ __launch_bounds__(256) void k_gemm(const float* __restrict__ A,
                                              const float* __restrict__ Bw,
                                              const float* __restrict__ bias) {
    __shared__ float As[BK][BM];   // transposed A tile
    __shared__ float Bs[BK][BN];
    const int bn = blockIdx.x, bm = blockIdx.y;
    const int tid = threadIdx.x;
    const int tx = tid & 15, ty = tid >> 4;   // 16x16 thread grid, 8x8 micro-tile each

    float acc[8][8];
    #pragma unroll
    for (int i = 0; i < 8; i++)
        #pragma unroll
        for (int j = 0; j < 8; j++) acc[i][j] = 0.f;

    const float* Ab = A + (size_t)bm * BM * KSUM;
    const float* Bb = Bw + (size_t)bn * BN;

    // per-thread tile-fragment addressing (constant across iterations)
    const int af0 = tid,        af1 = tid + 256;      // A: flat float4 ids
    const int ar0 = af0 >> 2,   ac0 = (af0 & 3) * 4;  // (m row, k col)
    const int ar1 = af1 >> 2,   ac1 = (af1 & 3) * 4;
    const int br0 = af0 >> 5,   bc0 = (af0 & 31) * 4; // B: (k row, n col)
    const int br1 = af1 >> 5,   bc1 = (af1 & 31) * 4;

    // ---- prologue: load k0 = 0 tiles straight into smem
    {
        float4 a0 = *(const float4*)(Ab + (size_t)ar0*KSUM + ac0);
        float4 a1 = *(const float4*)(Ab + (size_t)ar1*KSUM + ac1);
        As[ac0+0][ar0] = a0.x; As[ac0+1][ar0] = a0.y; As[ac0+2][ar0] = a0.z; As[ac0+3][ar0] = a0.w;
        As[ac1+0][ar1] = a1.x; As[ac1+1][ar1] = a1.y; As[ac1+2][ar1] = a1.z; As[ac1+3][ar1] = a1.w;
        *(float4*)(&Bs[br0][bc0]) = *(const float4*)(Bb + (size_t)br0*DSAE + bc0);
        *(float4*)(&Bs[br1][bc1]) = *(const float4*)(Bb + (size_t)br1*DSAE + bc1);
    }
    __syncthreads();

    for (int k0 = 0; k0 < KSUM; k0 += BK) {
        // ---- prefetch next tiles into registers (overlaps with compute below)
        float4 na0, na1, nb0, nb1;
        const bool more = (k0 + BK) < KSUM;
        if (more) {
            int kn = k0 + BK;
            na0 = *(const float4*)(Ab + (size_t)ar0*KSUM + kn + ac0);
            na1 = *(const float4*)(Ab + (size_t)ar1*KSUM + kn + ac1);
            nb0 = *(const float4*)(Bb + (size_t)(kn+br0)*DSAE + bc0);
            nb1 = *(const float4*)(Bb + (size_t)(kn+br1)*DSAE + bc1);
        }
        // ---- compute current tile
        #pragma unroll
        for (int kk = 0; kk < BK; kk++) {
            float a[8], b[8];
            *(float4*)(a)   = *(float4*)(&As[kk][ty*8]);
            *(float4*)(a+4) = *(float4*)(&As[kk][ty*8+4]);
            *(float4*)(b)   = *(float4*)(&Bs[kk][tx*8]);
            *(float4*)(b+4) = *(float4*)(&Bs[kk][tx*8+4]);
            #pragma unroll
            for (int i = 0; i < 8; i++)
                #pragma unroll
                for (int j = 0; j < 8; j++) acc[i][j] += a[i] * b[j];
        }
        __syncthreads();
        // ---- commit prefetched tiles
        if (more) {
            As[ac0+0][ar0] = na0.x; As[ac0+1][ar0] = na0.y; As[ac0+2][ar0] = na0.z; As[ac0+3][ar0] = na0.w;
            As[ac1+0][ar1] = na1.x; As[ac1+1][ar1] = na1.y; As[ac1+2][ar1] = na1.z; As[ac1+3][ar1] = na1.w;
            *(float4*)(&Bs[br0][bc0]) = nb0;
            *(float4*)(&Bs[br1][bc1]) = nb1;
        }
        __syncthreads();
    }

    // epilogue: + bias, store to g_pre
    #pragma unroll
    for (int i = 0; i < 8; i++) {
        int m = bm*BM + ty*8 + i;
        #pragma unroll
        for (int j = 0; j < 8; j += 4) {
            int n = bn*BN + tx*8 + j;
            float4 bv = *(const float4*)(bias + n);
            float4 o;
            o.x = acc[i][j+0] + bv.x; o.y = acc[i][j+1] + bv.y;
            o.z = acc[i][j+2] + bv.z; o.w = acc[i][j+3] + bv.w;
            *(float4*)(g_pre + (size_t)m*DSAE + n) = o;
        }
    }
}

// ---------------- K3: exact top-64 per row (radix select) + z write ----------------
__global__ __launch_bounds__(256) void k_topk(float* __restrict__ z_out) {
    const int b = blockIdx.x;
    const float* row = g_pre + (size_t)b * DSAE;
    const int tid = threadIdx.x;

    __shared__ int hist[256];
    __shared__ unsigned s_prefix;
    __shared__ int s_krem;

    if (tid == 0) { s_prefix = 0u; s_krem = TOPK; }
    __syncthreads();

    for (int pass = 0; pass < 4; pass++) {
        int shift = 24 - pass*8;
        unsigned pmask = (pass == 0) ? 0u : (0xFFFFFFFFu << (shift + 8));
        hist[tid] = 0;
        __syncthreads();
        unsigned pfx = s_prefix;
        for (int i = tid; i < DSAE; i += 256) {
            unsigned u = fkey(row[i]);
            if ((u & pmask) == pfx) atomicAdd(&hist[(u >> shift) & 255], 1);
        }
        __syncthreads();
        if (tid == 0) {
            int krem = s_krem, cum = 0, bin;
            for (bin = 255; bin >= 0; bin--) {
                if (cum + hist[bin] >= krem) break;
                cum += hist[bin];
            }
            s_prefix |= ((unsigned)bin) << shift;
            s_krem = krem - cum;
        }
        __syncthreads();
    }

    __shared__ int   s_idx[TOPK];
    __shared__ float s_v[TOPK];
    __shared__ int   s_eq_idx[TOPK];
    __shared__ int   s_cnt, s_eqc;
    if (tid == 0) { s_cnt = 0; s_eqc = 0; }
    __syncthreads();

    const unsigned thr = s_prefix;
    for (int i = tid; i < DSAE; i += 256) {
        float v = row[i];
        unsigned u = fkey(v);
        if (u > thr) {
            int pos = atomicAdd(&s_cnt, 1);
            if (pos < TOPK) { s_idx[pos] = i; s_v[pos] = v; }
        } else if (u == thr) {
            int e = atomicAdd(&s_eqc, 1);
            if (e < TOPK) s_eq_idx[e] = i;
        }
    }
    __syncthreads();

    if (tid == 0) {
        // append s_krem threshold-equal entries, lowest index first (matches lax.top_k ties)
        int n = s_eqc < TOPK ? s_eqc : TOPK;
        for (int a = 0; a < n; a++)
            for (int c = a+1; c < n; c++)
                if (s_eq_idx[c] < s_eq_idx[a]) { int t = s_eq_idx[a]; s_eq_idx[a] = s_eq_idx[c]; s_eq_idx[c] = t; }
        int base = s_cnt < TOPK ? s_cnt : TOPK;  // == TOPK - s_krem
        for (int a = 0; a < s_krem && base + a < TOPK; a++) {
            int i = s_eq_idx[a];
            s_idx[base+a] = i; s_v[base+a] = row[i];
        }
        // deterministic order: sort all 64 by index (bit-stable across graph replays)
        for (int a = 0; a < TOPK; a++)
            for (int c = a+1; c < TOPK; c++)
                if (s_idx[c] < s_idx[a]) {
                    int ti = s_idx[a]; s_idx[a] = s_idx[c]; s_idx[c] = ti;
                    float tv = s_v[a]; s_v[a] = s_v[c]; s_v[c] = tv;
                }
    }
    __syncthreads();

    if (tid < TOPK) {
        float v = s_v[tid];
        v = v > 0.f ? v : 0.f;                 // relu
        g_tk_idx[b*TOPK + tid] = s_idx[tid];
        g_tk_val[b*TOPK + tid] = v;
    }

    // z row: zeros then scatter relu'd values
    float* zr = z_out + (size_t)b * DSAE;
    for (int i = tid; i < DSAE; i += 256) zr[i] = 0.f;
    __syncthreads();
    if (tid < TOPK) {
        float v = s_v[tid];
        zr[s_idx[tid]] = v > 0.f ? v : 0.f;
    }
}

// ---------------- K4: sparse decode + per-(b,t) squared errors ----------------
__global__ __launch_bounds__(256) void k_dec(const float* __restrict__ x,
                                             const float* __restrict__ Wd0,
                                             const float* __restrict__ bd0,
                                             const float* __restrict__ Wd1,
                                             const float* __restrict__ bd1,
                                             float* __restrict__ xhat_out) {
    const int bt = blockIdx.x;
    const int b = bt >> 2, t = bt & 3;
    const int tid = threadIdx.x;

    __shared__ float s_val[TOPK];
    __shared__ int   s_p[TOPK];
    if (tid < TOPK) {
        int s = g_tk_idx[b*TOPK + tid];
        s_val[tid] = g_tk_val[b*TOPK + tid];
        s_p[tid] = g_inv[t*DSAE + s];
    }
    __syncthreads();

    float a0[3], a1[3];
    #pragma unroll
    for (int r = 0; r < 3; r++) {
        int d = tid + r*256;
        a0[r] = bd0[t*DIN + d];
        a1[r] = bd1[t*DIN + d];
    }
    for (int k = 0; k < TOPK; k++) {
        float v = s_val[k];
        int   p = s_p[k];
        const float* w1 = Wd1 + ((size_t)p*TDIM + t) * DIN;
        #pragma unroll
        for (int r = 0; r < 3; r++) a1[r] += v * w1[tid + r*256];
        if (p < PFX0) {   // uniform across block (p is shared)
            const float* w0 = Wd0 + ((size_t)p*TDIM + t) * DIN;
            #pragma unroll
            for (int r = 0; r < 3; r++) a0[r] += v * w0[tid + r*256];
        }
    }

    float e = 0.f;
    const float* xr = x + (size_t)bt * DIN;
    float* outr = xhat_out + (size_t)bt * DIN;
    #pragma unroll
    for (int r = 0; r < 3; r++) {
        int d = tid + r*256;
        float xv = xr[d];
        outr[d] = a1[r];
        float d0 = a0[r] - xv, d1 = a1[r] - xv;
        e += d0*d0 + d1*d1;
    }

    __shared__ float red[256];
    red[tid] = e;
    __syncthreads();
    for (int s = 128; s > 0; s >>= 1) {
        if (tid < s) red[tid] += red[tid + s];
        __syncthreads();
    }
    if (tid == 0) g_err[bt] = red[0];
}

// ---------------- K5: deterministic final loss reduction ----------------
__global__ void k_final(float* __restrict__ out) {
    __shared__ float red[256];
    int tid = threadIdx.x;
    float s = 0.f;
    for (int i = tid; i < NBT; i += 256) s += g_err[i];
    red[tid] = s;
    __syncthreads();
    for (int k = 128; k > 0; k >>= 1) {
        if (tid < k) red[tid] += red[tid + k];
        __syncthreads();
    }
    if (tid == 0) out[0] = red[0] / (float)(2 * TDIM * BATCH);
}

// ---------------- launch ----------------
extern "C" void kernel_launch(void* const* d_in, const int* in_sizes, int n_in,
                              void* d_out, int out_size) {
    const float* x     = (const float*)d_in[0];
    const float* W_enc = (const float*)d_in[1];
    const float* b_enc = (const float*)d_in[2];
    const float* W_d0  = (const float*)d_in[3];
    const float* b_d0  = (const float*)d_in[4];
    const float* W_d1  = (const float*)d_in[5];
    const float* b_d1  = (const float*)d_in[6];
    const int*   perm  = (const int*)d_in[7];

    float* out   = (float*)d_out;
    float* xhat  = out + 1;                               // (1024,4,768)
    float* z     = out + 1 + (size_t)BATCH*TDIM*DIN;      // (1024,16384)

    k_inv<<<(TDIM*DSAE + 255)/256, 256>>>(perm);
    k_gemm<<<dim3(DSAE/BN, BATCH/BM), 256>>>(x, W_enc, b_enc);
    k_topk<<<BATCH, 256>>>(z);
    k_dec<<<NBT, 256>>>(x, W_d0, b_d0, W_d1, b_d1, xhat);
    k_final<<<1, 256>>>(out);
}

// round 6
// speedup vs baseline: 2.2152x; 2.2152x over previous
#include <cuda_runtime.h>
#include <cuda_bf16.h>
#include <cstdint>

// ---------------- problem constants ----------------
#define BATCH   1024
#define TDIM    4
#define DIN     768
#define DSAE    16384
#define KSUM    (TDIM*DIN)       // 3072
#define TOPK    64
#define PFX0    8192
#define NBT     (BATCH*TDIM)     // 4096

// ---------------- device scratch ----------------
__device__ float g_pre[(size_t)BATCH*DSAE];
__device__ int   g_inv[TDIM*DSAE];
__device__ int   g_tk_idx[BATCH*TOPK];
__device__ float g_tk_val[BATCH*TOPK];
__device__ float g_err[NBT];

// bf16x2 split operands
__device__ __nv_bfloat16 gA1[(size_t)BATCH*KSUM];
__device__ __nv_bfloat16 gA2[(size_t)BATCH*KSUM];
__device__ __nv_bfloat16 gB1[(size_t)DSAE*KSUM];   // [n][k] K-major
__device__ __nv_bfloat16 gB2[(size_t)DSAE*KSUM];

// ---------------- helpers ----------------
__device__ __forceinline__ unsigned fkey(float f) {
    unsigned u = __float_as_uint(f);
    return (u & 0x80000000u) ? ~u : (u | 0x80000000u);
}
__device__ __forceinline__ uint32_t smem_u32(const void* p) {
    uint32_t a;
    asm("{ .reg .u64 t; cvta.to.shared.u64 t, %1; cvt.u32.u64 %0, t; }" : "=r"(a) : "l"(p));
    return a;
}
__device__ __forceinline__ void cp16(uint32_t s, const void* g) {
    asm volatile("cp.async.cg.shared.global [%0], [%1], 16;" :: "r"(s), "l"(g));
}
__device__ __forceinline__ void cp_commit() {
    asm volatile("cp.async.commit_group;" ::: "memory");
}
__device__ __forceinline__ void cp_wait1() {
    asm volatile("cp.async.wait_group 1;" ::: "memory");
}
__device__ __forceinline__ void ldm_x4(uint32_t* r, uint32_t addr) {
    asm volatile("ldmatrix.sync.aligned.m8n8.x4.shared.b16 {%0,%1,%2,%3}, [%4];"
        : "=r"(r[0]), "=r"(r[1]), "=r"(r[2]), "=r"(r[3]) : "r"(addr));
}
__device__ __forceinline__ void mma16816(float* d, const uint32_t* a, const uint32_t* b) {
    asm volatile("mma.sync.aligned.m16n8k16.row.col.f32.bf16.bf16.f32 "
        "{%0,%1,%2,%3}, {%4,%5,%6,%7}, {%8,%9}, {%0,%1,%2,%3};"
        : "+f"(d[0]), "+f"(d[1]), "+f"(d[2]), "+f"(d[3])
        : "r"(a[0]), "r"(a[1]), "r"(a[2]), "r"(a[3]), "r"(b[0]), "r"(b[1]));
}

// ---------------- K1: inverse permutation ----------------
__global__ void k_inv(const int* __restrict__ perm) {
    int i = blockIdx.x * blockDim.x + threadIdx.x;
    if (i < TDIM*DSAE) {
        int t = i / DSAE;
        g_inv[t*DSAE + perm[i]] = i % DSAE;
    }
}

// ---------------- split kernels (bf16x2) ----------------
__global__ __launch_bounds__(256) void k_splitA(const float* __restrict__ x) {
    int i = blockIdx.x * 256 + threadIdx.x;           // over 1024*3072
    float v = x[i];
    __nv_bfloat16 b1 = __float2bfloat16(v);
    float r1 = v - __bfloat162float(b1);
    gA1[i] = b1; gA2[i] = __float2bfloat16(r1);
}

__global__ __launch_bounds__(256) void k_splitB(const float* __restrict__ W) {
    __shared__ __nv_bfloat16 t1[32][34], t2[32][34];
    const int tx = threadIdx.x & 31, ty = threadIdx.x >> 5;   // 32x8
    const int nt = blockIdx.x * 32, kt = blockIdx.y * 32;
    #pragma unroll
    for (int r = 0; r < 4; r++) {
        int kl = ty + r*8;
        float v = W[(size_t)(kt + kl) * DSAE + nt + tx];
        __nv_bfloat16 b1 = __float2bfloat16(v);
        float r1 = v - __bfloat162float(b1);
        t1[kl][tx] = b1; t2[kl][tx] = __float2bfloat16(r1);
    }
    __syncthreads();
    #pragma unroll
    for (int r = 0; r < 4; r++) {
        int nl = ty + r*8;
        size_t o = (size_t)(nt + nl) * KSUM + kt + tx;
        gB1[o] = t1[tx][nl]; gB2[o] = t2[tx][nl];
    }
}

// ---------------- K2: bf16x2 HMMA GEMM  pre = X*W + bias ----------------
// CTA tile 128x128, 8 warps (2 M x 4 N), warp tile 64x32, BK=32,
// cp.async double-buffered smem, 80B-padded rows, plain ldmatrix frags.
#define ROWB    80                       // padded row stride (bytes) for 32-bf16 rows
#define TILEB   (128*ROWB)               // 10240 B: one 128x32 bf16 tile
#define STAGEB  (4*TILEB)                // A1,A2,B1,B2
#define NCHUNK  (KSUM/32)                // 96
#define GEMM_SMEM (2*STAGEB)             // 81920

__device__ __forceinline__ void load_stage(uint32_t sbase,
        const __nv_bfloat16* A1p, const __nv_bfloat16* A2p,
        const __nv_bfloat16* B1p, const __nv_bfloat16* B2p,
        int k0, int tid) {
    const __nv_bfloat16* srcs[4] = {A1p, A2p, B1p, B2p};
    #pragma unroll
    for (int t = 0; t < 4; t++) {
        uint32_t tb = sbase + t*TILEB;
        #pragma unroll
        for (int h = 0; h < 2; h++) {
            int c = tid + h*256;         // 512 16B chunks per tile
            int row = c >> 2, c4 = c & 3;
            cp16(tb + row*ROWB + c4*16,
                 srcs[t] + (size_t)row*KSUM + k0 + c4*8);
        }
    }
}

__global__ __launch_bounds__(256, 2) void k_gemm_mma(const float* __restrict__ bias) {
    extern __shared__ char smem[];
    const uint32_t s0 = smem_u32(smem);

    const int tid  = threadIdx.x;
    const int wid  = tid >> 5, lane = tid & 31;
    const int wm   = wid & 1, wn = wid >> 1;      // 2 x 4 warps

    // supergrouped rasterization: 4 M-blocks fastest, then N
    const int bx    = blockIdx.x;                 // 0..1023
    const int group = bx >> 9;                    // / 512
    const int within= bx & 511;
    const int m0    = ((group << 2) + (within & 3)) * 128;
    const int n0    = (within >> 2) * 128;

    // ldmatrix lane-address components
    const int g8 = lane >> 3, rl = lane & 7;      // quadrant, row-in-quadrant
    const uint32_t rowA = (uint32_t)((wm*64 + (g8 & 1)*8 + rl) * ROWB + (g8 >> 1)*16);
    const uint32_t rowB = (uint32_t)((wn*32 + (g8 >> 1)*8 + rl) * ROWB + (g8 & 1)*16);

    const __nv_bfloat16* A1p = gA1 + (size_t)m0 * KSUM;
    const __nv_bfloat16* A2p = gA2 + (size_t)m0 * KSUM;
    const __nv_bfloat16* B1p = gB1 + (size_t)n0 * KSUM;
    const __nv_bfloat16* B2p = gB2 + (size_t)n0 * KSUM;

    float acc[4][4][4];
    #pragma unroll
    for (int i = 0; i < 4; i++)
        #pragma unroll
        for (int j = 0; j < 4; j++)
            #pragma unroll
            for (int r = 0; r < 4; r++) acc[i][j][r] = 0.f;

    const uint32_t st[2] = {s0, s0 + STAGEB};

    load_stage(st[0], A1p, A2p, B1p, B2p, 0, tid);
    cp_commit();

    for (int c = 0; c < NCHUNK; c++) {
        if (c + 1 < NCHUNK)
            load_stage(st[(c+1)&1], A1p, A2p, B1p, B2p, (c+1)*32, tid);
        cp_commit();
        cp_wait1();
        __syncthreads();

        const uint32_t sb = st[c & 1];
        #pragma unroll
        for (int kk = 0; kk < 2; kk++) {
            uint32_t a[4][4], b[4][2];
            // A1 frags (4 m-tiles)
            #pragma unroll
            for (int mi = 0; mi < 4; mi++)
                ldm_x4(a[mi], sb + 0*TILEB + mi*(16*ROWB) + kk*32 + rowA);
            // B1 frags (2 x4 loads cover 4 n-tiles)
            #pragma unroll
            for (int np = 0; np < 2; np++)
                ldm_x4(&b[np*2][0], sb + 2*TILEB + np*(16*ROWB) + kk*32 + rowB);
            #pragma unroll
            for (int mi = 0; mi < 4; mi++)
                #pragma unroll
                for (int ni = 0; ni < 4; ni++)
                    mma16816(acc[mi][ni], a[mi], b[ni]);      // A1*B1
            // B2 frags
            #pragma unroll
            for (int np = 0; np < 2; np++)
                ldm_x4(&b[np*2][0], sb + 3*TILEB + np*(16*ROWB) + kk*32 + rowB);
            #pragma unroll
            for (int mi = 0; mi < 4; mi++)
                #pragma unroll
                for (int ni = 0; ni < 4; ni++)
                    mma16816(acc[mi][ni], a[mi], b[ni]);      // A1*B2
            // A2 frags, re-load B1
            #pragma unroll
            for (int mi = 0; mi < 4; mi++)
                ldm_x4(a[mi], sb + 1*TILEB + mi*(16*ROWB) + kk*32 + rowA);
            #pragma unroll
            for (int np = 0; np < 2; np++)
                ldm_x4(&b[np*2][0], sb + 2*TILEB + np*(16*ROWB) + kk*32 + rowB);
            #pragma unroll
            for (int mi = 0; mi < 4; mi++)
                #pragma unroll
                for (int ni = 0; ni < 4; ni++)
                    mma16816(acc[mi][ni], a[mi], b[ni]);      // A2*B1
        }
        __syncthreads();
    }

    // epilogue: +bias, store fp32
    const int cg = lane >> 2, ct = lane & 3;
    #pragma unroll
    for (int mi = 0; mi < 4; mi++) {
        int m = m0 + wm*64 + mi*16 + cg;
        float* row0 = g_pre + (size_t)m * DSAE + n0 + wn*32;
        float* row1 = row0 + (size_t)8 * DSAE;
        #pragma unroll
        for (int ni = 0; ni < 4; ni++) {
            int n = ni*8 + ct*2;
            float2 bv = *(const float2*)(bias + n0 + wn*32 + n);
            float2 v0, v1;
            v0.x = acc[mi][ni][0] + bv.x; v0.y = acc[mi][ni][1] + bv.y;
            v1.x = acc[mi][ni][2] + bv.x; v1.y = acc[mi][ni][3] + bv.y;
            *(float2*)(row0 + n) = v0;
            *(float2*)(row1 + n) = v1;
        }
    }
}

// ---------------- K3: exact top-64 per row (radix select) + z write ----------------
__global__ __launch_bounds__(256) void k_topk(float* __restrict__ z_out) {
    const int b = blockIdx.x;
    const float* row = g_pre + (size_t)b * DSAE;
    const int tid = threadIdx.x;

    __shared__ int hist[256];
    __shared__ unsigned s_prefix;
    __shared__ int s_krem;

    if (tid == 0) { s_prefix = 0u; s_krem = TOPK; }
    __syncthreads();

    for (int pass = 0; pass < 4; pass++) {
        int shift = 24 - pass*8;
        unsigned pmask = (pass == 0) ? 0u : (0xFFFFFFFFu << (shift + 8));
        hist[tid] = 0;
        __syncthreads();
        unsigned pfx = s_prefix;
        for (int i = tid; i < DSAE; i += 256) {
            unsigned u = fkey(row[i]);
            if ((u & pmask) == pfx) atomicAdd(&hist[(u >> shift) & 255], 1);
        }
        __syncthreads();
        if (tid == 0) {
            int krem = s_krem, cum = 0, bin;
            for (bin = 255; bin >= 0; bin--) {
                if (cum + hist[bin] >= krem) break;
                cum += hist[bin];
            }
            s_prefix |= ((unsigned)bin) << shift;
            s_krem = krem - cum;
        }
        __syncthreads();
    }

    __shared__ int   s_idx[TOPK];
    __shared__ float s_v[TOPK];
    __shared__ int   s_eq_idx[TOPK];
    __shared__ int   s_cnt, s_eqc;
    if (tid == 0) { s_cnt = 0; s_eqc = 0; }
    __syncthreads();

    const unsigned thr = s_prefix;
    for (int i = tid; i < DSAE; i += 256) {
        float v = row[i];
        unsigned u = fkey(v);
        if (u > thr) {
            int pos = atomicAdd(&s_cnt, 1);
            if (pos < TOPK) { s_idx[pos] = i; s_v[pos] = v; }
        } else if (u == thr) {
            int e = atomicAdd(&s_eqc, 1);
            if (e < TOPK) s_eq_idx[e] = i;
        }
    }
    __syncthreads();

    if (tid == 0) {
        int n = s_eqc < TOPK ? s_eqc : TOPK;
        for (int a = 0; a < n; a++)
            for (int c2 = a+1; c2 < n; c2++)
                if (s_eq_idx[c2] < s_eq_idx[a]) { int t = s_eq_idx[a]; s_eq_idx[a] = s_eq_idx[c2]; s_eq_idx[c2] = t; }
        int base = s_cnt < TOPK ? s_cnt : TOPK;
        for (int a = 0; a < s_krem && base + a < TOPK; a++) {
            int i = s_eq_idx[a];
            s_idx[base+a] = i; s_v[base+a] = row[i];
        }
        for (int a = 0; a < TOPK; a++)
            for (int c2 = a+1; c2 < TOPK; c2++)
                if (s_idx[c2] < s_idx[a]) {
                    int ti = s_idx[a]; s_idx[a] = s_idx[c2]; s_idx[c2] = ti;
                    float tv = s_v[a]; s_v[a] = s_v[c2]; s_v[c2] = tv;
                }
    }
    __syncthreads();

    if (tid < TOPK) {
        float v = s_v[tid];
        v = v > 0.f ? v : 0.f;
        g_tk_idx[b*TOPK + tid] = s_idx[tid];
        g_tk_val[b*TOPK + tid] = v;
    }

    float* zr = z_out + (size_t)b * DSAE;
    for (int i = tid; i < DSAE; i += 256) zr[i] = 0.f;
    __syncthreads();
    if (tid < TOPK) {
        float v = s_v[tid];
        zr[s_idx[tid]] = v > 0.f ? v : 0.f;
    }
}

// ---------------- K4: sparse decode + per-(b,t) squared errors ----------------
__global__ __launch_bounds__(256) void k_dec(const float* __restrict__ x,
                                             const float* __restrict__ Wd0,
                                             const float* __restrict__ bd0,
                                             const float* __restrict__ Wd1,
                                             const float* __restrict__ bd1,
                                             float* __restrict__ xhat_out) {
    const int bt = blockIdx.x;
    const int b = bt >> 2, t = bt & 3;
    const int tid = threadIdx.x;

    __shared__ float s_val[TOPK];
    __shared__ int   s_p[TOPK];
    if (tid < TOPK) {
        int s = g_tk_idx[b*TOPK + tid];
        s_val[tid] = g_tk_val[b*TOPK + tid];
        s_p[tid] = g_inv[t*DSAE + s];
    }
    __syncthreads();

    float a0[3], a1[3];
    #pragma unroll
    for (int r = 0; r < 3; r++) {
        int d = tid + r*256;
        a0[r] = bd0[t*DIN + d];
        a1[r] = bd1[t*DIN + d];
    }
    for (int k = 0; k < TOPK; k++) {
        float v = s_val[k];
        int   p = s_p[k];
        const float* w1 = Wd1 + ((size_t)p*TDIM + t) * DIN;
        #pragma unroll
        for (int r = 0; r < 3; r++) a1[r] += v * w1[tid + r*256];
        if (p < PFX0) {
            const float* w0 = Wd0 + ((size_t)p*TDIM + t) * DIN;
            #pragma unroll
            for (int r = 0; r < 3; r++) a0[r] += v * w0[tid + r*256];
        }
    }

    float e = 0.f;
    const float* xr = x + (size_t)bt * DIN;
    float* outr = xhat_out + (size_t)bt * DIN;
    #pragma unroll
    for (int r = 0; r < 3; r++) {
        int d = tid + r*256;
        float xv = xr[d];
        outr[d] = a1[r];
        float d0 = a0[r] - xv, d1 = a1[r] - xv;
        e += d0*d0 + d1*d1;
    }

    __shared__ float red[256];
    red[tid] = e;
    __syncthreads();
    for (int s = 128; s > 0; s >>= 1) {
        if (tid < s) red[tid] += red[tid + s];
        __syncthreads();
    }
    if (tid == 0) g_err[bt] = red[0];
}

// ---------------- K5: deterministic final loss reduction ----------------
__global__ void k_final(float* __restrict__ out) {
    __shared__ float red[256];
    int tid = threadIdx.x;
    float s = 0.f;
    for (int i = tid; i < NBT; i += 256) s += g_err[i];
    red[tid] = s;
    __syncthreads();
    for (int k = 128; k > 0; k >>= 1) {
        if (tid < k) red[tid] += red[tid + k];
        __syncthreads();
    }
    if (tid == 0) out[0] = red[0] / (float)(2 * TDIM * BATCH);
}

// ---------------- launch ----------------
extern "C" void kernel_launch(void* const* d_in, const int* in_sizes, int n_in,
                              void* d_out, int out_size) {
    const float* x     = (const float*)d_in[0];
    const float* W_enc = (const float*)d_in[1];
    const float* b_enc = (const float*)d_in[2];
    const float* W_d0  = (const float*)d_in[3];
    const float* b_d0  = (const float*)d_in[4];
    const float* W_d1  = (const float*)d_in[5];
    const float* b_d1  = (const float*)d_in[6];
    const int*   perm  = (const int*)d_in[7];

    float* out   = (float*)d_out;
    float* xhat  = out + 1;
    float* z     = out + 1 + (size_t)BATCH*TDIM*DIN;

    cudaFuncSetAttribute(k_gemm_mma, cudaFuncAttributeMaxDynamicSharedMemorySize, GEMM_SMEM);

    k_inv<<<(TDIM*DSAE + 255)/256, 256>>>(perm);
    k_splitA<<<(BATCH*KSUM)/256, 256>>>(x);
    k_splitB<<<dim3(DSAE/32, KSUM/32), 256>>>(W_enc);
    k_gemm_mma<<<1024, 256, GEMM_SMEM>>>(b_enc);
    k_topk<<<BATCH, 256>>>(z);
    k_dec<<<NBT, 256>>>(x, W_d0, b_d0, W_d1, b_d1, xhat);
    k_final<<<1, 256>>>(out);
}